// round 8
// baseline (speedup 1.0000x reference)
#include <cuda_runtime.h>
#include <cstddef>

// Problem constants (B=64, T=2048, J=24, C=4*J+3=99)
#define NB 64
#define NT 2048
#define HT (NT / 2)            // float2 pairs per channel row
#define NJ 24
#define NC 99
#define TPB 128
#define GX (HT / TPB)          // 8
#define NBLK (GX * NB)         // 512 partial sums

__device__ float g_partials[NBLK];
__device__ unsigned int g_count = 0;

// ---------------- packed f32x2 helpers (Blackwell sm_100a) ----------------
typedef unsigned long long f2;

__device__ __forceinline__ f2 f2pk(float lo, float hi) {
    f2 r; asm("mov.b64 %0, {%1, %2};" : "=l"(r) : "f"(lo), "f"(hi)); return r;
}
__device__ __forceinline__ void f2un(f2 v, float& lo, float& hi) {
    asm("mov.b64 {%0, %1}, %2;" : "=f"(lo), "=f"(hi) : "l"(v));
}
__device__ __forceinline__ f2 f2add(f2 a, f2 b) {
    f2 r; asm("add.rn.f32x2 %0, %1, %2;" : "=l"(r) : "l"(a), "l"(b)); return r;
}
__device__ __forceinline__ f2 f2neg(f2 a) {
    f2 r; asm("xor.b64 %0, %1, 0x8000000080000000;" : "=l"(r) : "l"(a)); return r;
}
__device__ __forceinline__ f2 f2sub(f2 a, f2 b) { return f2add(a, f2neg(b)); }
__device__ __forceinline__ f2 f2abs(f2 a) {
    f2 r; asm("and.b64 %0, %1, 0x7FFFFFFF7FFFFFFF;" : "=l"(r) : "l"(a)); return r;
}
__device__ __forceinline__ f2 f2mul(f2 a, f2 b) {
    f2 r; asm("mul.rn.f32x2 %0, %1, %2;" : "=l"(r) : "l"(a), "l"(b)); return r;
}
__device__ __forceinline__ f2 f2fma(f2 a, f2 b, f2 c) {
    f2 r; asm("fma.rn.f32x2 %0, %1, %2, %3;" : "=l"(r) : "l"(a), "l"(b), "l"(c)); return r;
}
__device__ __forceinline__ float frcp(float x) {
    float r; asm("rcp.approx.f32 %0, %1;" : "=f"(r) : "f"(x)); return r;
}

__device__ __forceinline__ float warp_sum(float v) {
#pragma unroll
    for (int o = 16; o > 0; o >>= 1) v += __shfl_down_sync(0xffffffffu, v, o);
    return v;
}

// quat->rotmat on a (t0,t1)-packed quaternion. q[4], m[9] all f32x2.
__device__ __forceinline__ void quat2mat2(const f2 q[4], f2 m[9]) {
    const f2 w = q[0], x = q[1], y = q[2], z = q[3];
    const f2 xx = f2mul(x, x), yy = f2mul(y, y), zz = f2mul(z, z);
    const f2 xy = f2mul(x, y), xz = f2mul(x, z), yz = f2mul(y, z);
    const f2 wx = f2mul(w, x), wy = f2mul(w, y), wz = f2mul(w, z);
    const f2 n  = f2fma(w, w, f2add(f2add(xx, yy), zz));
    float nl, nh; f2un(n, nl, nh);
    const float sl = 2.0f * frcp(nl), sh = 2.0f * frcp(nh);
    const f2 s   = f2pk(sl, sh);
    const f2 ns  = f2pk(-sl, -sh);
    const f2 one = f2pk(1.0f, 1.0f);
    m[0] = f2fma(ns, f2add(yy, zz), one);
    m[1] = f2mul(s,  f2sub(xy, wz));
    m[2] = f2mul(s,  f2add(xz, wy));
    m[3] = f2mul(s,  f2add(xy, wz));
    m[4] = f2fma(ns, f2add(xx, zz), one);
    m[5] = f2mul(s,  f2sub(yz, wx));
    m[6] = f2mul(s,  f2sub(xz, wy));
    m[7] = f2mul(s,  f2add(yz, wx));
    m[8] = f2fma(ns, f2add(xx, yy), one);
}

__device__ __forceinline__ void mat3mul2(const f2 a[9], const f2 b[9], f2 c[9]) {
#pragma unroll
    for (int r = 0; r < 3; r++)
#pragma unroll
        for (int cc = 0; cc < 3; cc++)
            c[r * 3 + cc] = f2fma(a[r * 3 + 0], b[0 * 3 + cc],
                            f2fma(a[r * 3 + 1], b[1 * 3 + cc],
                            f2mul(a[r * 3 + 2], b[2 * 3 + cc])));
}

// One FK step for one stream (Y or X). psrc/dst are compile-time constants
// after full unroll. Tsh/Rsh are this stream's park columns [e][TPB].
__device__ __forceinline__ void fk_stream(
    int psrc, int dst, const f2 q[4], const f2* __restrict__ off,
    f2 Treg[9], f2 Rreg[3], f2 (*Tsh)[TPB], f2 (*Rsh)[TPB],
    int tid, f2 r[3])
{
    f2 m[9];
    quat2mat2(q, m);

    if (dst == 0) {
        // Leaf: r = Treg*(m*off) + Rreg; no new T needed.
        f2 mo[3];
#pragma unroll
        for (int rr = 0; rr < 3; rr++)
            mo[rr] = f2fma(m[rr * 3 + 2], off[2],
                     f2fma(m[rr * 3 + 1], off[1],
                     f2mul(m[rr * 3 + 0], off[0])));
#pragma unroll
        for (int rr = 0; rr < 3; rr++)
            r[rr] = f2fma(Treg[rr * 3 + 2], mo[2],
                    f2fma(Treg[rr * 3 + 1], mo[1],
                    f2fma(Treg[rr * 3 + 0], mo[0], Rreg[rr])));
        return;
    }

    f2 T[9];
    if (psrc == 0) {
#pragma unroll
        for (int e = 0; e < 9; e++) T[e] = m[e];
    } else if (psrc == 1) {
        f2 a[9];
#pragma unroll
        for (int e = 0; e < 9; e++) a[e] = Tsh[e][tid];
        mat3mul2(a, m, T);
    } else {
        mat3mul2(Treg, m, T);
    }

#pragma unroll
    for (int rr = 0; rr < 3; rr++)
        r[rr] = f2fma(T[rr * 3 + 2], off[2],
                f2fma(T[rr * 3 + 1], off[1],
                f2mul(T[rr * 3 + 0], off[0])));
    if (psrc == 1) {
#pragma unroll
        for (int rr = 0; rr < 3; rr++) r[rr] = f2add(r[rr], Rsh[rr][tid]);
    } else if (psrc == 2) {
#pragma unroll
        for (int rr = 0; rr < 3; rr++) r[rr] = f2add(r[rr], Rreg[rr]);
    }

    if (dst == 1) {
#pragma unroll
        for (int e = 0; e < 9; e++) Treg[e] = T[e];
#pragma unroll
        for (int rr = 0; rr < 3; rr++) Rreg[rr] = r[rr];
    } else {   // dst == 2: park branch-point state
#pragma unroll
        for (int e = 0; e < 9; e++) Tsh[e][tid] = T[e];
#pragma unroll
        for (int rr = 0; rr < 3; rr++) Rsh[rr][tid] = r[rr];
    }
}

__global__ void __launch_bounds__(TPB, 4) motion_loss_kernel(
    const float* __restrict__ Ym, const float* __restrict__ Xm,
    const float* __restrict__ Yt, const float* __restrict__ Xt,
    const float* __restrict__ jw, float* __restrict__ out)
{
    __shared__ f2    swp[NJ];          // broadcast-packed joint weights
    __shared__ f2    soY[NJ * 3];      // broadcast-packed Yt offsets
    __shared__ f2    soX[NJ * 3];      // broadcast-packed Xt offsets
    __shared__ f2    TshY[9][TPB], RshY[3][TPB];   // parked branch-point (Y)
    __shared__ f2    TshX[9][TPB], RshX[3][TPB];   // parked branch-point (X)
    __shared__ float red[TPB / 32];
    __shared__ bool  is_last;

    const int b   = blockIdx.y;
    const int gp  = blockIdx.x * TPB + threadIdx.x;   // float2-pair index in [0,HT)
    const int tid = threadIdx.x;

    if (tid < NJ) { const float w = jw[tid]; swp[tid] = f2pk(w, w); }
    if (tid < NJ * 3) {
        const float oy = Yt[b * NJ * 3 + tid];
        const float ox = Xt[b * NJ * 3 + tid];
        soY[tid] = f2pk(oy, oy);
        soX[tid] = f2pk(ox, ox);
    }
    __syncthreads();

    // View channel rows as packed (t, t+1) 64-bit pairs.
    const f2* __restrict__ yb2 = (const f2*)(Ym + (size_t)b * NC * NT);
    const f2* __restrict__ xb2 = (const f2*)(Xm + (size_t)b * NC * NT);

    f2 lrot2 = 0ull, lfk2 = 0ull, lpos2 = 0ull;

    f2 TregY[9], RregY[3];
    f2 TregX[9], RregX[3];

    // TOPOLOGY = {-1,0,0,0,1,2,3,4,5,6,7,8,9,9,9,12,13,14,16,17,18,19,20,21}
    // DFS processing order; leaves = {10,11,15,22,23}.
    constexpr int ORDER[NJ] = {0,1,4,7,10, 2,5,8,11, 3,6,9, 12,15, 13,16,18,20,22, 14,17,19,21,23};
    // PSRC: 0 = root, 1 = shared park, 2 = register slot
    constexpr int PSRC[NJ]  = {0,1,2,2,2, 1,2,2,2, 1,2,2, 1,2, 1,2,2,2,2, 1,2,2,2,2};
    // DST: 0 = leaf (discard), 1 = register, 2 = shared park
    constexpr int DST[NJ]   = {2,1,1,1,0, 1,1,1,0, 1,1,2, 1,0, 1,1,1,1,0, 1,1,1,1,0};

#pragma unroll
    for (int i = 0; i < NJ; i++) {
        const int j = ORDER[i];

        f2 qY[4], qX[4];
#pragma unroll
        for (int k = 0; k < 4; k++) {
            qY[k] = yb2[(size_t)(4 * j + k) * HT + gp];
            qX[k] = xb2[(size_t)(4 * j + k) * HT + gp];
        }

        f2 rd2 = f2abs(f2sub(qY[0], qX[0]));
#pragma unroll
        for (int k = 1; k < 4; k++) rd2 = f2add(rd2, f2abs(f2sub(qY[k], qX[k])));
        lrot2 = f2fma(swp[j], rd2, lrot2);

        f2 rY[3], rX[3];
        fk_stream(PSRC[i], DST[i], qY, &soY[j * 3], TregY, RregY, TshY, RshY, tid, rY);
        fk_stream(PSRC[i], DST[i], qX, &soX[j * 3], TregX, RregX, TshX, RshX, tid, rX);

        f2 fkd2 = f2add(f2add(f2abs(f2sub(rY[0], rX[0])),
                              f2abs(f2sub(rY[1], rX[1]))),
                              f2abs(f2sub(rY[2], rX[2])));
        lfk2 = f2fma(swp[j], fkd2, lfk2);
    }

#pragma unroll
    for (int d = 0; d < 3; d++)
        lpos2 = f2add(lpos2, f2abs(f2sub(yb2[(size_t)(4 * NJ + d) * HT + gp],
                                         xb2[(size_t)(4 * NJ + d) * HT + gp])));

    // loss = B1*sum_rot/(B*T*J*4) + B2*sum_fk/(B*T*J*3) + sum_pos/(B*T*3)
    const float CR = 1.0f / (64.0f * 2048.0f * 24.0f * 4.0f);
    const float CF = 1.0f / (64.0f * 2048.0f * 24.0f * 3.0f);
    const float CP = 1.0f / (64.0f * 2048.0f * 3.0f);
    float r0, r1, f0, f1, p0, p1;
    f2un(lrot2, r0, r1); f2un(lfk2, f0, f1); f2un(lpos2, p0, p1);
    float v = (r0 + r1) * CR + (f0 + f1) * CF + (p0 + p1) * CP;

    // ---- block reduction ----
    v = warp_sum(v);
    if ((tid & 31) == 0) red[tid >> 5] = v;
    __syncthreads();
    if (tid == 0) {
        float s = 0.0f;
#pragma unroll
        for (int wgi = 0; wgi < TPB / 32; wgi++) s += red[wgi];
        g_partials[blockIdx.y * GX + blockIdx.x] = s;
        __threadfence();
        const unsigned int old = atomicAdd(&g_count, 1u);
        is_last = (old == NBLK - 1);
    }
    __syncthreads();

    // ---- last block folds all partials (deterministic fixed-order sum) ----
    if (is_last) {
        float s = 0.0f;
#pragma unroll
        for (int k = 0; k < NBLK / TPB; k++) s += g_partials[tid + k * TPB];
        s = warp_sum(s);
        if ((tid & 31) == 0) red[tid >> 5] = s;
        __syncthreads();
        if (tid == 0) {
            float tot = 0.0f;
#pragma unroll
            for (int wgi = 0; wgi < TPB / 32; wgi++) tot += red[wgi];
            out[0] = tot;
            g_count = 0;   // reset for next graph replay
        }
    }
}

extern "C" void kernel_launch(void* const* d_in, const int* in_sizes, int n_in,
                              void* d_out, int out_size) {
    const float* Ym = (const float*)d_in[0];
    const float* Xm = (const float*)d_in[1];
    const float* Yt = (const float*)d_in[2];
    const float* Xt = (const float*)d_in[3];
    const float* jw = (const float*)d_in[4];

    dim3 grid(GX, NB);
    motion_loss_kernel<<<grid, TPB>>>(Ym, Xm, Yt, Xt, jw, (float*)d_out);
}

// round 11
// speedup vs baseline: 1.4655x; 1.4655x over previous
#include <cuda_runtime.h>
#include <cstddef>

// Problem constants (B=64, T=2048, J=24, C=4*J+3=99)
#define NB 64
#define NT 2048
#define NJ 24
#define NC 99
#define TPB 128
#define GX (NT / TPB)          // 16
#define NBLK (GX * NB)         // 1024 partial sums
#define NSTAGE 4               // cp.async pipeline depth (4 KB per stage)

__device__ float g_partials[NBLK];
__device__ unsigned int g_count = 0;

// ---------------- packed f32x2 helpers (Blackwell sm_100a) ----------------
typedef unsigned long long f2;

__device__ __forceinline__ f2 f2pk(float lo, float hi) {
    f2 r; asm("mov.b64 %0, {%1, %2};" : "=l"(r) : "f"(lo), "f"(hi)); return r;
}
__device__ __forceinline__ void f2un(f2 v, float& lo, float& hi) {
    asm("mov.b64 {%0, %1}, %2;" : "=f"(lo), "=f"(hi) : "l"(v));
}
__device__ __forceinline__ f2 f2add(f2 a, f2 b) {
    f2 r; asm("add.rn.f32x2 %0, %1, %2;" : "=l"(r) : "l"(a), "l"(b)); return r;
}
__device__ __forceinline__ f2 f2neg(f2 a) {
    f2 r; asm("xor.b64 %0, %1, 0x8000000080000000;" : "=l"(r) : "l"(a)); return r;
}
__device__ __forceinline__ f2 f2sub(f2 a, f2 b) { return f2add(a, f2neg(b)); }
__device__ __forceinline__ f2 f2mul(f2 a, f2 b) {
    f2 r; asm("mul.rn.f32x2 %0, %1, %2;" : "=l"(r) : "l"(a), "l"(b)); return r;
}
__device__ __forceinline__ f2 f2fma(f2 a, f2 b, f2 c) {
    f2 r; asm("fma.rn.f32x2 %0, %1, %2, %3;" : "=l"(r) : "l"(a), "l"(b), "l"(c)); return r;
}
__device__ __forceinline__ float frcp(float x) {
    float r; asm("rcp.approx.f32 %0, %1;" : "=f"(r) : "f"(x)); return r;
}

__device__ __forceinline__ float warp_sum(float v) {
#pragma unroll
    for (int o = 16; o > 0; o >>= 1) v += __shfl_down_sync(0xffffffffu, v, o);
    return v;
}

// quat->rotmat on a packed (Y,X) pair. q[4], m[9] all f32x2.
__device__ __forceinline__ void quat2mat2(const f2 q[4], f2 m[9]) {
    const f2 w = q[0], x = q[1], y = q[2], z = q[3];
    const f2 xx = f2mul(x, x), yy = f2mul(y, y), zz = f2mul(z, z);
    const f2 xy = f2mul(x, y), xz = f2mul(x, z), yz = f2mul(y, z);
    const f2 wx = f2mul(w, x), wy = f2mul(w, y), wz = f2mul(w, z);
    const f2 n  = f2fma(w, w, f2add(f2add(xx, yy), zz));
    float nl, nh; f2un(n, nl, nh);
    const float sl = 2.0f * frcp(nl), sh = 2.0f * frcp(nh);
    const f2 s   = f2pk(sl, sh);
    const f2 ns  = f2pk(-sl, -sh);
    const f2 one = f2pk(1.0f, 1.0f);
    m[0] = f2fma(ns, f2add(yy, zz), one);
    m[1] = f2mul(s,  f2sub(xy, wz));
    m[2] = f2mul(s,  f2add(xz, wy));
    m[3] = f2mul(s,  f2add(xy, wz));
    m[4] = f2fma(ns, f2add(xx, zz), one);
    m[5] = f2mul(s,  f2sub(yz, wx));
    m[6] = f2mul(s,  f2sub(xz, wy));
    m[7] = f2mul(s,  f2add(yz, wx));
    m[8] = f2fma(ns, f2add(xx, yy), one);
}

__device__ __forceinline__ void mat3mul2(const f2 a[9], const f2 b[9], f2 c[9]) {
#pragma unroll
    for (int r = 0; r < 3; r++)
#pragma unroll
        for (int cc = 0; cc < 3; cc++)
            c[r * 3 + cc] = f2fma(a[r * 3 + 0], b[0 * 3 + cc],
                            f2fma(a[r * 3 + 1], b[1 * 3 + cc],
                            f2mul(a[r * 3 + 2], b[2 * 3 + cc])));
}

__device__ __forceinline__ void cp16(unsigned int dst_smem, const float* src) {
    asm volatile("cp.async.cg.shared.global [%0], [%1], 16;"
                 :: "r"(dst_smem), "l"(src));
}
__device__ __forceinline__ void cp_commit() {
    asm volatile("cp.async.commit_group;");
}
__device__ __forceinline__ void cp_wait2() {
    asm volatile("cp.async.wait_group 2;");
}

// Issue one stage: joint j's 8 quat channel rows (4 Y + 4 X) -> buffer buf.
// 2x 16B cp.async per thread (256 segments of 16B = 4 KB).
__device__ __forceinline__ void issue_stage(
    const float* __restrict__ yb0, const float* __restrict__ xb0,
    unsigned int stg_base, int tid, int j, int buf)
{
#pragma unroll
    for (int c = 0; c < 2; c++) {
        const int seg = 2 * tid + c;          // 0..255
        const int row = seg >> 5;             // 0..7
        const int col = seg & 31;             // 16B unit within 512B row
        const int ch  = 4 * j + (row & 3);
        const float* base = (row < 4) ? yb0 : xb0;
        const float* src  = base + (size_t)ch * NT + col * 4;
        cp16(stg_base + (unsigned int)(buf * 4096 + row * 512 + col * 16), src);
    }
}

__global__ void __launch_bounds__(TPB) motion_loss_kernel(
    const float* __restrict__ Ym, const float* __restrict__ Xm,
    const float* __restrict__ Yt, const float* __restrict__ Xt,
    const float* __restrict__ jw, float* __restrict__ out)
{
    // Stage buffer: [stage][row 0-7][t 0-127]; rows 0-3 = Y quat channels,
    // rows 4-7 = X quat channels. 4 KB per stage.
    __shared__ float stg[NSTAGE][8][TPB];
    __shared__ float sw[NJ];
    __shared__ f2    so[NJ * 3];     // packed (Yt, Xt) offsets for this batch
    __shared__ float red[TPB / 32];
    __shared__ bool  is_last;

    const int b   = blockIdx.y;
    const int t0  = blockIdx.x * TPB;
    const int tid = threadIdx.x;

    const float* yb0 = Ym + (size_t)b * NC * NT + t0;   // + channel*NT + t
    const float* xb0 = Xm + (size_t)b * NC * NT + t0;

    // TOPOLOGY = {-1,0,0,0,1,2,3,4,5,6,7,8,9,9,9,12,13,14,16,17,18,19,20,21}
    // 3-slot breadth layout (identical to the 34.8us champion).
    constexpr int SLOT[NJ]  = {0,1,2,0,1,2,0,1,2,0,-1,-1,1,2,0,-1,1,2,0,1,2,0,-1,-1};
    constexpr int PSLOT[NJ] = {-1,0,0,0,1,2,0,1,2,0,1,2,0,0,0,1,2,0,1,2,0,1,2,0};

    const unsigned int stg_base = (unsigned int)__cvta_generic_to_shared(&stg[0][0][0]);

    // Prologue: stages 0..NSTAGE-2 in flight (group index == stage index).
#pragma unroll
    for (int s = 0; s < NSTAGE - 1; s++) {
        issue_stage(yb0, xb0, stg_base, tid, s, s);
        cp_commit();
    }

    if (tid < NJ) sw[tid] = jw[tid];
    if (tid < NJ * 3) so[tid] = f2pk(Yt[b * NJ * 3 + tid], Xt[b * NJ * 3 + tid]);

    float lrot = 0.0f, lfk = 0.0f;

    f2 Ts[3][9];
    f2 Rs[3][3];

#pragma unroll
    for (int i = 0; i < NJ; i++) {
        // Stage i resident (own copies), then barrier: everyone's copies of
        // stage i visible AND all warps finished reading buffer (i-1)%NSTAGE.
        cp_wait2();
        __syncthreads();

        // Refill: stage i+NSTAGE-1 into buffer (i-1)%NSTAGE (safe per above).
        if (i + NSTAGE - 1 < NJ)
            issue_stage(yb0, xb0, stg_base, tid, i + NSTAGE - 1, (i + NSTAGE - 1) % NSTAGE);
        cp_commit();                                // unconditional: keeps group==stage

        const int buf = i % NSTAGE;
        const float wj = sw[i];

        f2 q[4];
        float rd = 0.0f;
#pragma unroll
        for (int k = 0; k < 4; k++) {
            const float a = stg[buf][k][tid];
            const float c = stg[buf][4 + k][tid];
            rd += fabsf(a - c);
            q[k] = f2pk(a, c);
        }
        lrot += wj * rd;

        f2 m[9];
        quat2mat2(q, m);

        f2 c[9];
        if (i == 0) {
#pragma unroll
            for (int e = 0; e < 9; e++) c[e] = m[e];
        } else {
            mat3mul2(Ts[PSLOT[i]], m, c);
        }

        f2 r[3];
#pragma unroll
        for (int rr = 0; rr < 3; rr++)
            r[rr] = f2fma(c[rr * 3 + 2], so[i * 3 + 2],
                    f2fma(c[rr * 3 + 1], so[i * 3 + 1],
                    f2mul(c[rr * 3 + 0], so[i * 3 + 0])));
        if (i > 0) {
            const int ps = PSLOT[i];
#pragma unroll
            for (int rr = 0; rr < 3; rr++) r[rr] = f2add(r[rr], Rs[ps][rr]);
        }

        float fkd = 0.0f;
#pragma unroll
        for (int rr = 0; rr < 3; rr++) {
            float ylo, xhi; f2un(r[rr], ylo, xhi);
            fkd += fabsf(ylo - xhi);
        }
        lfk += wj * fkd;

        if (SLOT[i] >= 0) {
            const int s = SLOT[i];
#pragma unroll
            for (int e = 0; e < 9; e++) Ts[s][e] = c[e];
#pragma unroll
            for (int rr = 0; rr < 3; rr++) Rs[s][rr] = r[rr];
        }
    }

    float lpos = 0.0f;
#pragma unroll
    for (int d = 0; d < 3; d++)
        lpos += fabsf(yb0[(size_t)(4 * NJ + d) * NT + tid] -
                      xb0[(size_t)(4 * NJ + d) * NT + tid]);

    // loss = B1*sum_rot/(B*T*J*4) + B2*sum_fk/(B*T*J*3) + sum_pos/(B*T*3)
    const float CR = 1.0f / (64.0f * 2048.0f * 24.0f * 4.0f);
    const float CF = 1.0f / (64.0f * 2048.0f * 24.0f * 3.0f);
    const float CP = 1.0f / (64.0f * 2048.0f * 3.0f);
    float v = lrot * CR + lfk * CF + lpos * CP;

    // ---- block reduction ----
    v = warp_sum(v);
    if ((tid & 31) == 0) red[tid >> 5] = v;
    __syncthreads();
    if (tid == 0) {
        float s = 0.0f;
#pragma unroll
        for (int wgi = 0; wgi < TPB / 32; wgi++) s += red[wgi];
        g_partials[blockIdx.y * GX + blockIdx.x] = s;
        __threadfence();
        const unsigned int old = atomicAdd(&g_count, 1u);
        is_last = (old == NBLK - 1);
    }
    __syncthreads();

    // ---- last block folds all partials (deterministic fixed-order sum) ----
    if (is_last) {
        float s = 0.0f;
#pragma unroll
        for (int k = 0; k < NBLK / TPB; k++) s += g_partials[tid + k * TPB];
        s = warp_sum(s);
        if ((tid & 31) == 0) red[tid >> 5] = s;
        __syncthreads();
        if (tid == 0) {
            float tot = 0.0f;
#pragma unroll
            for (int wgi = 0; wgi < TPB / 32; wgi++) tot += red[wgi];
            out[0] = tot;
            g_count = 0;   // reset for next graph replay
        }
    }
}

extern "C" void kernel_launch(void* const* d_in, const int* in_sizes, int n_in,
                              void* d_out, int out_size) {
    const float* Ym = (const float*)d_in[0];
    const float* Xm = (const float*)d_in[1];
    const float* Yt = (const float*)d_in[2];
    const float* Xt = (const float*)d_in[3];
    const float* jw = (const float*)d_in[4];

    dim3 grid(GX, NB);
    motion_loss_kernel<<<grid, TPB>>>(Ym, Xm, Yt, Xt, jw, (float*)d_out);
}